// round 8
// baseline (speedup 1.0000x reference)
#include <cuda_runtime.h>
#include <cuda_bf16.h>

#define S_LEN 256
#define BATCH 64
#define FEAT  256
#define HID   768
#define G4    3072
#define TLEN  32
#define NBLK  128
#define TM    6
#define OUT_ENC_OFF (TLEN*BATCH*FEAT)
#define ENC_SZ (BATCH*HID)

// ---- static device scratch (no allocations allowed) ----
__device__ __align__(16) float g_xproj[(size_t)S_LEN*BATCH*G4];  // 201 MB
__device__ __align__(16) float g_hA[2][BATCH*HID];
__device__ __align__(16) float g_c[BATCH*HID];
__device__ __align__(16) float g_dh[2][HID];
__device__ unsigned g_bar_count;
__device__ volatile unsigned g_bar_gen;

__device__ __forceinline__ float sigf(float x) { return 1.0f / (1.0f + expf(-x)); }
__device__ __forceinline__ float warp_sum(float v) {
#pragma unroll
    for (int o = 16; o; o >>= 1) v += __shfl_xor_sync(0xffffffffu, v, o);
    return v;
}

__device__ __forceinline__ void gsync(unsigned &my_gen) {
    __syncthreads();
    if (threadIdx.x == 0) {
        __threadfence();
        if (atomicAdd(&g_bar_count, 1u) == NBLK - 1u) {
            atomicExch(&g_bar_count, 0u);
            __threadfence();
            g_bar_gen = my_gen + 1u;
        } else {
            while (g_bar_gen == my_gen) { __nanosleep(64); }
            __threadfence();
        }
    }
    my_gen += 1u;
    __syncthreads();
}

// ---------------------------------------------------------------------------
// Kernel 1: xproj[m][j] = x[m][:] @ Wih0[j][:] + (bih0[j]+bhh0[j])
// M=16384, N=3072, K=256. 64x64 tile, 256 threads, 4x4 micro.
// ---------------------------------------------------------------------------
__global__ void __launch_bounds__(256) xproj_gemm(
    const float* __restrict__ X, const float* __restrict__ W,
    const float* __restrict__ bA, const float* __restrict__ bB)
{
    __shared__ __align__(16) float sX[16 * 68];
    __shared__ __align__(16) float sW[16 * 68];
    const int tid = threadIdx.x;
    const int jBase = blockIdx.x * 64;
    const int mBase = blockIdx.y * 64;
    const int tx = tid & 15, ty = tid >> 4;
    const int lrow = tid >> 2, lqk = tid & 3;

    float acc[4][4];
#pragma unroll
    for (int i = 0; i < 4; i++)
#pragma unroll
        for (int r = 0; r < 4; r++) acc[i][r] = 0.0f;

    for (int k0 = 0; k0 < 256; k0 += 16) {
        float4 xv = *(const float4*)(X + (size_t)(mBase + lrow) * 256 + k0 + lqk * 4);
        float4 wv = *(const float4*)(W + (size_t)(jBase + lrow) * 256 + k0 + lqk * 4);
        __syncthreads();
        int kk = lqk * 4;
        sX[(kk + 0) * 68 + lrow] = xv.x; sX[(kk + 1) * 68 + lrow] = xv.y;
        sX[(kk + 2) * 68 + lrow] = xv.z; sX[(kk + 3) * 68 + lrow] = xv.w;
        sW[(kk + 0) * 68 + lrow] = wv.x; sW[(kk + 1) * 68 + lrow] = wv.y;
        sW[(kk + 2) * 68 + lrow] = wv.z; sW[(kk + 3) * 68 + lrow] = wv.w;
        __syncthreads();
#pragma unroll
        for (int k = 0; k < 16; k++) {
            float4 a = *(const float4*)(sX + k * 68 + ty * 4);
            float4 b = *(const float4*)(sW + k * 68 + tx * 4);
            acc[0][0] += a.x * b.x; acc[0][1] += a.x * b.y; acc[0][2] += a.x * b.z; acc[0][3] += a.x * b.w;
            acc[1][0] += a.y * b.x; acc[1][1] += a.y * b.y; acc[1][2] += a.y * b.z; acc[1][3] += a.y * b.w;
            acc[2][0] += a.z * b.x; acc[2][1] += a.z * b.y; acc[2][2] += a.z * b.z; acc[2][3] += a.z * b.w;
            acc[3][0] += a.w * b.x; acc[3][1] += a.w * b.y; acc[3][2] += a.w * b.z; acc[3][3] += a.w * b.w;
        }
    }
    float4 b1 = *(const float4*)(bA + jBase + tx * 4);
    float4 b2 = *(const float4*)(bB + jBase + tx * 4);
#pragma unroll
    for (int i = 0; i < 4; i++) {
        float4 o;
        o.x = acc[i][0] + b1.x + b2.x; o.y = acc[i][1] + b1.y + b2.y;
        o.z = acc[i][2] + b1.z + b2.z; o.w = acc[i][3] + b1.w + b2.w;
        *(float4*)(g_xproj + (size_t)(mBase + ty * 4 + i) * G4 + jBase + tx * 4) = o;
    }
}

// ---------------------------------------------------------------------------
// Gate tile: all 64 b x this block's 24 j-rows (4 gates x TM m-rows), K=768.
// Result -> sGt[b*24 + gate*6 + ml].
// ---------------------------------------------------------------------------
__device__ __forceinline__ void gates_tile(
    const float* __restrict__ hin, const float* __restrict__ W,
    const float* __restrict__ addX, const float* __restrict__ bA,
    const float* __restrict__ bB, int m0, int tid,
    float* sHs, float* sWs, float* sGt)
{
    const int tbp = tid & 15, tjp = tid >> 4;
    const int b0 = tbp * 4, j0 = tjp * 3;
    float acc[12];
#pragma unroll
    for (int i = 0; i < 12; i++) acc[i] = 0.0f;

    for (int k0 = 0; k0 < HID; k0 += 32) {
        __syncthreads();
#pragma unroll
        for (int q = 0; q < 4; q++) {
            int p = tid + 128 * q;
            int bb = p >> 3, qk = p & 7;
            float4 v = __ldcg((const float4*)(hin + (size_t)bb * HID + k0 + qk * 4));
            int kk = qk * 4;
            sHs[(kk + 0) * 68 + bb] = v.x; sHs[(kk + 1) * 68 + bb] = v.y;
            sHs[(kk + 2) * 68 + bb] = v.z; sHs[(kk + 3) * 68 + bb] = v.w;
        }
        for (int p = tid; p < 192; p += 128) {
            int jj = p >> 3, qk = p & 7;
            int g = jj / 6, ml = jj - g * 6;
            float4 v = *(const float4*)(W + (size_t)(g * HID + m0 + ml) * HID + k0 + qk * 4);
            *(float4*)(sWs + jj * 36 + qk * 4) = v;
        }
        __syncthreads();
#pragma unroll 8
        for (int k = 0; k < 32; k++) {
            float4 av = *(const float4*)(sHs + k * 68 + b0);
            float w0 = sWs[(j0 + 0) * 36 + k];
            float w1 = sWs[(j0 + 1) * 36 + k];
            float w2 = sWs[(j0 + 2) * 36 + k];
            acc[0] += av.x * w0; acc[1] += av.y * w0; acc[2]  += av.z * w0; acc[3]  += av.w * w0;
            acc[4] += av.x * w1; acc[5] += av.y * w1; acc[6]  += av.z * w1; acc[7]  += av.w * w1;
            acc[8] += av.x * w2; acc[9] += av.y * w2; acc[10] += av.z * w2; acc[11] += av.w * w2;
        }
    }
    __syncthreads();
#pragma unroll
    for (int r = 0; r < 3; r++) {
        int jj = j0 + r;
        int g = jj / 6, ml = jj - g * 6;
        int jglob = g * HID + m0 + ml;
        if (addX) {
#pragma unroll
            for (int i = 0; i < 4; i++)
                sGt[(b0 + i) * 24 + jj] = acc[r * 4 + i] + addX[(size_t)(b0 + i) * G4 + jglob];
        } else {
            float bb = bA[jglob] + bB[jglob];
#pragma unroll
            for (int i = 0; i < 4; i++)
                sGt[(b0 + i) * 24 + jj] = acc[r * 4 + i] + bb;
        }
    }
    __syncthreads();
}

// ---------------------------------------------------------------------------
// Kernel 2: persistent — encoder recurrence + stacked layers + decoder + head
// ---------------------------------------------------------------------------
__global__ void __launch_bounds__(128, 1) lstm_persistent(
    const float* __restrict__ Whh0,
    const float* __restrict__ eWih, const float* __restrict__ eBih,
    const float* __restrict__ eBhh,
    const float* __restrict__ dWih, const float* __restrict__ dBih,
    const float* __restrict__ dBhh,
    const float* __restrict__ linW, const float* __restrict__ linB,
    float* __restrict__ out, int out_size)
{
    __shared__ __align__(16) float sHs[32 * 68];
    __shared__ __align__(16) float sWs[24 * 36];
    __shared__ float sGt[64 * 24];

    const int tid = threadIdx.x;
    const int blk = blockIdx.x;
    const int m0 = blk * TM;
    const int lane = tid & 31, warp = tid >> 5;
    unsigned my_gen = g_bar_gen;

    // init: zero h[0], c, decoder h
    {
        int base = blk * 384;
#pragma unroll
        for (int q = 0; q < 3; q++) {
            int i = base + tid + 128 * q;
            g_hA[0][i] = 0.0f;
            g_c[i] = 0.0f;
        }
        if (blk < 6) g_dh[0][blk * 128 + tid] = 0.0f;
    }
    gsync(my_gen);

    const bool wrEnc = (out_size >= OUT_ENC_OFF + 3 * ENC_SZ);
    int cur = 0;

    // ---- Phase A: encoder layer 0, 256 serial steps ----
    for (int t = 0; t < S_LEN; t++) {
        gates_tile(g_hA[cur], Whh0, g_xproj + (size_t)t * BATCH * G4,
                   nullptr, nullptr, m0, tid, sHs, sWs, sGt);
#pragma unroll
        for (int q = 0; q < 3; q++) {
            int idx = tid + 128 * q;
            int b = idx / 6, ml = idx - (idx / 6) * 6;
            int m = m0 + ml;
            float iv = sGt[b * 24 + 0  + ml];
            float fv = sGt[b * 24 + 6  + ml];
            float gv = sGt[b * 24 + 12 + ml];
            float ov = sGt[b * 24 + 18 + ml];
            float c = sigf(fv) * g_c[b * HID + m] + sigf(iv) * tanhf(gv);
            g_c[b * HID + m] = c;
            g_hA[cur ^ 1][b * HID + m] = sigf(ov) * tanhf(c);
        }
        gsync(my_gen);
        cur ^= 1;
    }

    if (wrEnc) {
#pragma unroll
        for (int q = 0; q < 3; q++) {
            int idx = tid + 128 * q;
            int b = idx / 6, ml = idx - (idx / 6) * 6;
            out[OUT_ENC_OFF + b * HID + m0 + ml] = g_hA[cur][b * HID + m0 + ml];
        }
    }

    // ---- Phase C: encoder layers 1..2 (zero state -> f-gate dead) ----
    for (int l = 0; l < 2; l++) {
        gates_tile(g_hA[cur], eWih + (size_t)l * G4 * HID,
                   nullptr, eBih + l * G4, eBhh + l * G4, m0, tid, sHs, sWs, sGt);
#pragma unroll
        for (int q = 0; q < 3; q++) {
            int idx = tid + 128 * q;
            int b = idx / 6, ml = idx - (idx / 6) * 6;
            int m = m0 + ml;
            float iv = sGt[b * 24 + 0  + ml];
            float gv = sGt[b * 24 + 12 + ml];
            float ov = sGt[b * 24 + 18 + ml];
            float c = sigf(iv) * tanhf(gv);
            float h = sigf(ov) * tanhf(c);
            g_hA[cur ^ 1][b * HID + m] = h;
            if (wrEnc) out[OUT_ENC_OFF + (l + 1) * ENC_SZ + b * HID + m] = h;
        }
        gsync(my_gen);
        cur ^= 1;
    }

    // ---- Phase D: decoder. Batch-independent, layers independent, only the
    // last layer (l=2) chain feeds the head; f-gate dead (c_prev==0). ----
    const int gw = blk * 4 + warp;  // 0..511
    int dc = 0;
    for (int t = 0; t < TLEN; t++) {
        const float* hsrc = g_dh[dc];
        for (int m = gw; m < HID; m += 512) {
            const float* wi = dWih + ((size_t)2 * G4 + 0 * HID + m) * HID;
            const float* wg = dWih + ((size_t)2 * G4 + 2 * HID + m) * HID;
            const float* wo = dWih + ((size_t)2 * G4 + 3 * HID + m) * HID;
            float ai = 0.0f, ag = 0.0f, ao = 0.0f;
            for (int k = lane; k < HID; k += 32) {
                float hv = __ldcg(hsrc + k);
                ai += wi[k] * hv; ag += wg[k] * hv; ao += wo[k] * hv;
            }
            ai = warp_sum(ai); ag = warp_sum(ag); ao = warp_sum(ao);
            if (lane == 0) {
                int bi = 2 * G4 + m;
                float iv = ai + dBih[bi] + dBhh[bi];
                float gv = ag + dBih[bi + 2 * HID] + dBhh[bi + 2 * HID];
                float ov = ao + dBih[bi + 3 * HID] + dBhh[bi + 3 * HID];
                float c = sigf(iv) * tanhf(gv);
                g_dh[dc ^ 1][m] = sigf(ov) * tanhf(c);
            }
        }
        gsync(my_gen);
        if (gw < FEAT) {
            const float* wr = linW + (size_t)gw * HID;
            float a = 0.0f;
            for (int k = lane; k < HID; k += 32) a += wr[k] * __ldcg(g_dh[dc ^ 1] + k);
            a = warp_sum(a) + linB[gw];
            float* op = out + (size_t)t * BATCH * FEAT + gw;
            op[(size_t)lane * FEAT] = a;
            op[(size_t)(lane + 32) * FEAT] = a;
        }
        dc ^= 1;
    }
}

extern "C" void kernel_launch(void* const* d_in, const int* in_sizes, int n_in,
                              void* d_out, int out_size) {
    const float* x      = (const float*)d_in[0];
    const float* eWih0  = (const float*)d_in[1];
    const float* eWhh0  = (const float*)d_in[2];
    const float* eBih0  = (const float*)d_in[3];
    const float* eBhh0  = (const float*)d_in[4];
    const float* eWih   = (const float*)d_in[5];
    // d_in[6] = e_Whh : unused (zero-state layers)
    const float* eBih   = (const float*)d_in[7];
    const float* eBhh   = (const float*)d_in[8];
    const float* dWih   = (const float*)d_in[9];
    // d_in[10] = d_Whh : unused (decoder never carries state into W_hh)
    const float* dBih   = (const float*)d_in[11];
    const float* dBhh   = (const float*)d_in[12];
    const float* linW   = (const float*)d_in[13];
    const float* linB   = (const float*)d_in[14];
    float* out = (float*)d_out;

    dim3 g1(G4 / 64, (S_LEN * BATCH) / 64);
    xproj_gemm<<<g1, 256>>>(x, eWih0, eBih0, eBhh0);
    lstm_persistent<<<NBLK, 128>>>(eWhh0, eWih, eBih, eBhh,
                                   dWih, dBih, dBhh, linW, linB, out, out_size);
}

// round 10
// speedup vs baseline: 1.4089x; 1.4089x over previous
#include <cuda_runtime.h>
#include <cuda_bf16.h>
#include <cstdint>

typedef unsigned long long ull;

#define S_LEN 256
#define BATCH 64
#define FEAT  256
#define HID   768
#define G4    3072
#define TLEN  32
#define NBLK  128
#define TM    6
#define KHALF 384
#define OUT_ENC_OFF (TLEN*BATCH*FEAT)
#define ENC_SZ (BATCH*HID)

// dynamic smem layout (bytes)
#define SW2_STRIDE 772                       // ulls per jj row (pad: conflict-free)
#define OFF_W2   0
#define SZ_W2    (24*SW2_STRIDE*8)           // 148224
#define OFF_H    (OFF_W2 + SZ_W2)
#define SZ_H     (2*32*68*4)                 // 17408
#define OFF_GT   (OFF_H + SZ_H)
#define SZ_GT    (1536*4)
#define OFF_PART (OFF_GT + SZ_GT)
#define SZ_PART  (1536*4)
#define OFF_C    (OFF_PART + SZ_PART)
#define SZ_C     (384*4)
#define SMEM_TOTAL (OFF_C + SZ_C)            // 179456

// ---- static device scratch ----
// xproj stored PERMUTED: [t][blk][b][jj]  (jj = gate*6 + ml), so each block's
// per-step addend slice is 1536 contiguous floats.
__device__ __align__(16) float g_xproj[(size_t)S_LEN*NBLK*BATCH*24];
__device__ __align__(16) float g_hA[2][BATCH*HID];
__device__ __align__(16) float g_dh[2][HID];
__device__ unsigned g_bar_count;
__device__ volatile unsigned g_bar_gen;

__device__ __forceinline__ float sigf(float x) { return 1.0f / (1.0f + expf(-x)); }
__device__ __forceinline__ float warp_sum(float v) {
#pragma unroll
    for (int o = 16; o; o >>= 1) v += __shfl_xor_sync(0xffffffffu, v, o);
    return v;
}

// packed f32x2 helpers
__device__ __forceinline__ void ffma2(ull &acc, ull a, ull b) {
    asm("fma.rn.f32x2 %0, %1, %2, %0;" : "+l"(acc) : "l"(a), "l"(b));
}
__device__ __forceinline__ ull dup2(float x) {
    ull r; asm("mov.b64 %0, {%1, %1};" : "=l"(r) : "f"(x)); return r;
}
__device__ __forceinline__ float2 unpack2(ull v) {
    float2 r; asm("mov.b64 {%0, %1}, %2;" : "=f"(r.x), "=f"(r.y) : "l"(v)); return r;
}

__device__ __forceinline__ void gsync(unsigned &my_gen) {
    __syncthreads();
    if (threadIdx.x == 0) {
        __threadfence();
        if (atomicAdd(&g_bar_count, 1u) == NBLK - 1u) {
            atomicExch(&g_bar_count, 0u);
            __threadfence();
            g_bar_gen = my_gen + 1u;
        } else {
            while (g_bar_gen == my_gen) { __nanosleep(64); }
            __threadfence();
        }
    }
    my_gen += 1u;
    __syncthreads();
}

// ---------------------------------------------------------------------------
// Kernel 1: xproj = x @ Wih0^T + (bih0+bhh0), output permuted to [t][blk][b][jj]
// M=16384, N=3072, K=256. 64x64 tile, 256 threads, FFMA2 micro 4m x (2x j-pairs).
// ---------------------------------------------------------------------------
__global__ void __launch_bounds__(256) xproj_gemm(
    const float* __restrict__ X, const float* __restrict__ W,
    const float* __restrict__ bA, const float* __restrict__ bB)
{
    __shared__ __align__(16) float sX[16 * 68];
    __shared__ __align__(16) float sW[16 * 68];
    const int tid = threadIdx.x;
    const int jBase = blockIdx.x * 64;
    const int mBase = blockIdx.y * 64;
    const int tx = tid & 15, ty = tid >> 4;
    const int lrow = tid >> 2, lqk = tid & 3;

    ull acc[4][2];
#pragma unroll
    for (int i = 0; i < 4; i++) { acc[i][0] = 0ull; acc[i][1] = 0ull; }

    for (int k0 = 0; k0 < 256; k0 += 16) {
        float4 xv = *(const float4*)(X + (size_t)(mBase + lrow) * 256 + k0 + lqk * 4);
        float4 wv = *(const float4*)(W + (size_t)(jBase + lrow) * 256 + k0 + lqk * 4);
        __syncthreads();
        int kk = lqk * 4;
        sX[(kk + 0) * 68 + lrow] = xv.x; sX[(kk + 1) * 68 + lrow] = xv.y;
        sX[(kk + 2) * 68 + lrow] = xv.z; sX[(kk + 3) * 68 + lrow] = xv.w;
        sW[(kk + 0) * 68 + lrow] = wv.x; sW[(kk + 1) * 68 + lrow] = wv.y;
        sW[(kk + 2) * 68 + lrow] = wv.z; sW[(kk + 3) * 68 + lrow] = wv.w;
        __syncthreads();
#pragma unroll
        for (int k = 0; k < 16; k++) {
            float4 a = *(const float4*)(sX + k * 68 + ty * 4);
            ulonglong2 w = *(const ulonglong2*)(sW + k * 68 + tx * 4);
            ull a0 = dup2(a.x), a1 = dup2(a.y), a2 = dup2(a.z), a3 = dup2(a.w);
            ffma2(acc[0][0], a0, w.x); ffma2(acc[0][1], a0, w.y);
            ffma2(acc[1][0], a1, w.x); ffma2(acc[1][1], a1, w.y);
            ffma2(acc[2][0], a2, w.x); ffma2(acc[2][1], a2, w.y);
            ffma2(acc[3][0], a3, w.x); ffma2(acc[3][1], a3, w.y);
        }
    }
    float4 b1 = *(const float4*)(bA + jBase + tx * 4);
    float4 b2 = *(const float4*)(bB + jBase + tx * 4);
    float bias[4] = { b1.x + b2.x, b1.y + b2.y, b1.z + b2.z, b1.w + b2.w };
#pragma unroll
    for (int i = 0; i < 4; i++) {
        int m = mBase + ty * 4 + i;
        int t = m >> 6, b = m & 63;
        float2 p0 = unpack2(acc[i][0]);
        float2 p1 = unpack2(acc[i][1]);
        float v[4] = { p0.x, p0.y, p1.x, p1.y };
#pragma unroll
        for (int q = 0; q < 4; q++) {
            int j = jBase + tx * 4 + q;
            int gate = j / HID;
            int r = j - gate * HID;
            int blkj = r / 6;
            int ml = r - blkj * 6;
            g_xproj[(((size_t)t * NBLK + blkj) * BATCH + b) * 24 + gate * 6 + ml] = v[q] + bias[q];
        }
    }
}

// ---------------------------------------------------------------------------
// Persistent-kernel helpers (dynamic smem)
// ---------------------------------------------------------------------------
__device__ __forceinline__ void load_weights(
    const float* __restrict__ W, int m0, int tid, ull* sW2)
{
    for (int idx = tid; idx < 24 * HID; idx += 256) {
        int jj = idx / HID;
        int k = idx - jj * HID;
        int gate = jj / 6, ml = jj - gate * 6;
        float w = W[(size_t)(gate * HID + m0 + ml) * HID + k];
        sW2[(size_t)jj * SW2_STRIDE + k] = dup2(w);
    }
}

// gates for all 64 b x this block's 24 gate-rows; 256 threads (2-way K-split)
__device__ __forceinline__ void gates_step(
    const float* __restrict__ hin, const float* __restrict__ addX,
    const float* __restrict__ bA, const float* __restrict__ bB,
    int m0, int tid, const ull* sW2, float* sH, float* sGt, float* sPart)
{
    const int g  = tid >> 7;           // K-half 0/1
    const int wt = tid & 127;
    const int b0 = (wt & 15) * 4;
    const int j0 = (wt >> 4) * 3;
    const int kq = wt >> 4;            // staging k-slot 0..7
    float* sHg = sH + g * (32 * 68);

    ull acc[6] = {0ull,0ull,0ull,0ull,0ull,0ull};

    // prefetch iter 0
    const float* hb = hin + b0 * HID + g * KHALF + kq * 4;
    float4 L0 = __ldcg((const float4*)(hb + 0 * HID));
    float4 L1 = __ldcg((const float4*)(hb + 1 * HID));
    float4 L2 = __ldcg((const float4*)(hb + 2 * HID));
    float4 L3 = __ldcg((const float4*)(hb + 3 * HID));

#pragma unroll 1
    for (int it = 0; it < 12; ++it) {
        __syncthreads();
        int krow = kq * 4;
        *(float4*)(sHg + (krow + 0) * 68 + b0) = make_float4(L0.x, L1.x, L2.x, L3.x);
        *(float4*)(sHg + (krow + 1) * 68 + b0) = make_float4(L0.y, L1.y, L2.y, L3.y);
        *(float4*)(sHg + (krow + 2) * 68 + b0) = make_float4(L0.z, L1.z, L2.z, L3.z);
        *(float4*)(sHg + (krow + 3) * 68 + b0) = make_float4(L0.w, L1.w, L2.w, L3.w);
        __syncthreads();
        if (it + 1 < 12) {
            const float* hb2 = hin + b0 * HID + g * KHALF + (it + 1) * 32 + kq * 4;
            L0 = __ldcg((const float4*)(hb2 + 0 * HID));
            L1 = __ldcg((const float4*)(hb2 + 1 * HID));
            L2 = __ldcg((const float4*)(hb2 + 2 * HID));
            L3 = __ldcg((const float4*)(hb2 + 3 * HID));
        }
        const ull* w0p = sW2 + (size_t)j0 * SW2_STRIDE + g * KHALF + it * 32;
        const ull* w1p = w0p + SW2_STRIDE;
        const ull* w2p = w1p + SW2_STRIDE;
#pragma unroll
        for (int k = 0; k < 32; ++k) {
            ulonglong2 av = *(const ulonglong2*)(sHg + k * 68 + b0);
            ull w0 = w0p[k], w1 = w1p[k], w2 = w2p[k];
            ffma2(acc[0], av.x, w0); ffma2(acc[1], av.y, w0);
            ffma2(acc[2], av.x, w1); ffma2(acc[3], av.y, w1);
            ffma2(acc[4], av.x, w2); ffma2(acc[5], av.y, w2);
        }
    }

    if (g == 1) {
#pragma unroll
        for (int r = 0; r < 3; ++r) {
            float2 p0 = unpack2(acc[r * 2 + 0]);
            float2 p1 = unpack2(acc[r * 2 + 1]);
            float* d = sPart + (j0 + r) * 64 + b0;
            d[0] = p0.x; d[1] = p0.y; d[2] = p1.x; d[3] = p1.y;
        }
    }
    __syncthreads();
    if (g == 0) {
#pragma unroll
        for (int r = 0; r < 3; ++r) {
            int jj = j0 + r;
            float2 p0 = unpack2(acc[r * 2 + 0]);
            float2 p1 = unpack2(acc[r * 2 + 1]);
            const float* pp = sPart + jj * 64 + b0;
            float v[4] = { p0.x + pp[0], p0.y + pp[1], p1.x + pp[2], p1.y + pp[3] };
            if (addX) {
#pragma unroll
                for (int i = 0; i < 4; i++)
                    sGt[(b0 + i) * 24 + jj] = v[i] + addX[(b0 + i) * 24 + jj];
            } else {
                int gate = jj / 6, ml = jj - gate * 6;
                float bb = bA[gate * HID + m0 + ml] + bB[gate * HID + m0 + ml];
#pragma unroll
                for (int i = 0; i < 4; i++)
                    sGt[(b0 + i) * 24 + jj] = v[i] + bb;
            }
        }
    }
    __syncthreads();
}

// ---------------------------------------------------------------------------
// Kernel 2: persistent — encoder recurrence + stacked layers + decoder + head
// ---------------------------------------------------------------------------
__global__ void __launch_bounds__(256, 1) lstm_persistent(
    const float* __restrict__ Whh0,
    const float* __restrict__ eWih, const float* __restrict__ eBih,
    const float* __restrict__ eBhh,
    const float* __restrict__ dWih, const float* __restrict__ dBih,
    const float* __restrict__ dBhh,
    const float* __restrict__ linW, const float* __restrict__ linB,
    float* __restrict__ out, int out_size)
{
    extern __shared__ __align__(16) unsigned char smem[];
    ull*   sW2   = (ull*)(smem + OFF_W2);
    float* sH    = (float*)(smem + OFF_H);
    float* sGt   = (float*)(smem + OFF_GT);
    float* sPart = (float*)(smem + OFF_PART);
    float* sC    = (float*)(smem + OFF_C);

    const int tid = threadIdx.x;
    const int blk = blockIdx.x;
    const int m0 = blk * TM;
    const int lane = tid & 31, warp = tid >> 5;
    unsigned my_gen = g_bar_gen;

    // init: zero h[0] slice, smem c, decoder h
    for (int i = blk * 384 + tid; i < blk * 384 + 384; i += 256) g_hA[0][i] = 0.0f;
    for (int i = tid; i < 384; i += 256) sC[i] = 0.0f;
    if (blk < 3) g_dh[0][blk * 256 + tid] = 0.0f;

    // load Whh0 (dup'd) into smem — stays for all 256 steps
    load_weights(Whh0, m0, tid, sW2);
    gsync(my_gen);

    const bool wrEnc = (out_size >= OUT_ENC_OFF + 3 * ENC_SZ);
    int cur = 0;

    // ---- Phase A: encoder layer 0, 256 serial steps ----
#pragma unroll 1
    for (int t = 0; t < S_LEN; t++) {
        const float* addX = g_xproj + ((size_t)t * NBLK + blk) * (BATCH * 24);
        gates_step(g_hA[cur], addX, nullptr, nullptr, m0, tid, sW2, sH, sGt, sPart);
        for (int idx = tid; idx < 384; idx += 256) {
            int b = idx / 6, ml = idx - (idx / 6) * 6;
            float iv = sGt[b * 24 + ml];
            float fv = sGt[b * 24 + 6 + ml];
            float gv = sGt[b * 24 + 12 + ml];
            float ov = sGt[b * 24 + 18 + ml];
            float c = sigf(fv) * sC[idx] + sigf(iv) * tanhf(gv);
            sC[idx] = c;
            g_hA[cur ^ 1][b * HID + m0 + ml] = sigf(ov) * tanhf(c);
        }
        gsync(my_gen);
        cur ^= 1;
    }

    if (wrEnc) {
        for (int idx = tid; idx < 384; idx += 256) {
            int b = idx / 6, ml = idx - (idx / 6) * 6;
            out[OUT_ENC_OFF + b * HID + m0 + ml] = g_hA[cur][b * HID + m0 + ml];
        }
    }

    // ---- Phase C: encoder layers 1..2 (zero state -> f-gate dead) ----
    for (int l = 0; l < 2; l++) {
        load_weights(eWih + (size_t)l * G4 * HID, m0, tid, sW2);
        __syncthreads();
        gates_step(g_hA[cur], nullptr, eBih + l * G4, eBhh + l * G4,
                   m0, tid, sW2, sH, sGt, sPart);
        for (int idx = tid; idx < 384; idx += 256) {
            int b = idx / 6, ml = idx - (idx / 6) * 6;
            float iv = sGt[b * 24 + ml];
            float gv = sGt[b * 24 + 12 + ml];
            float ov = sGt[b * 24 + 18 + ml];
            float c = sigf(iv) * tanhf(gv);
            float h = sigf(ov) * tanhf(c);
            g_hA[cur ^ 1][b * HID + m0 + ml] = h;
            if (wrEnc) out[OUT_ENC_OFF + (l + 1) * ENC_SZ + b * HID + m0 + ml] = h;
        }
        gsync(my_gen);
        cur ^= 1;
    }

    // ---- Phase D: decoder. Batch-independent, only layer-2 chain matters,
    // f-gate dead (c_prev == 0). One B=1 matvec chain + broadcast head. ----
    const int gw = blk * 8 + warp;  // 0..1023 global warps
    int dc = 0;
    for (int t = 0; t < TLEN; t++) {
        const float* hsrc = g_dh[dc];
        for (int m = gw; m < HID; m += NBLK * 8) {
            const float* wi = dWih + ((size_t)2 * G4 + 0 * HID + m) * HID;
            const float* wg = dWih + ((size_t)2 * G4 + 2 * HID + m) * HID;
            const float* wo = dWih + ((size_t)2 * G4 + 3 * HID + m) * HID;
            float ai = 0.0f, ag = 0.0f, ao = 0.0f;
            for (int k = lane; k < HID; k += 32) {
                float hv = __ldcg(hsrc + k);
                ai += wi[k] * hv; ag += wg[k] * hv; ao += wo[k] * hv;
            }
            ai = warp_sum(ai); ag = warp_sum(ag); ao = warp_sum(ao);
            if (lane == 0) {
                int bi = 2 * G4 + m;
                float iv = ai + dBih[bi] + dBhh[bi];
                float gv = ag + dBih[bi + 2 * HID] + dBhh[bi + 2 * HID];
                float ov = ao + dBih[bi + 3 * HID] + dBhh[bi + 3 * HID];
                float c = sigf(iv) * tanhf(gv);
                g_dh[dc ^ 1][m] = sigf(ov) * tanhf(c);
            }
        }
        gsync(my_gen);
        if (gw < FEAT) {
            const float* wr = linW + (size_t)gw * HID;
            float a = 0.0f;
            for (int k = lane; k < HID; k += 32) a += wr[k] * __ldcg(g_dh[dc ^ 1] + k);
            a = warp_sum(a) + linB[gw];
            float* op = out + (size_t)t * BATCH * FEAT + gw;
            op[(size_t)lane * FEAT] = a;
            op[(size_t)(lane + 32) * FEAT] = a;
        }
        dc ^= 1;
    }
}

extern "C" void kernel_launch(void* const* d_in, const int* in_sizes, int n_in,
                              void* d_out, int out_size) {
    const float* x      = (const float*)d_in[0];
    const float* eWih0  = (const float*)d_in[1];
    const float* eWhh0  = (const float*)d_in[2];
    const float* eBih0  = (const float*)d_in[3];
    const float* eBhh0  = (const float*)d_in[4];
    const float* eWih   = (const float*)d_in[5];
    // d_in[6] = e_Whh : unused (zero-state layers)
    const float* eBih   = (const float*)d_in[7];
    const float* eBhh   = (const float*)d_in[8];
    const float* dWih   = (const float*)d_in[9];
    // d_in[10] = d_Whh : unused (decoder never carries state into W_hh)
    const float* dBih   = (const float*)d_in[11];
    const float* dBhh   = (const float*)d_in[12];
    const float* linW   = (const float*)d_in[13];
    const float* linB   = (const float*)d_in[14];
    float* out = (float*)d_out;

    cudaFuncSetAttribute(lstm_persistent,
                         cudaFuncAttributeMaxDynamicSharedMemorySize, SMEM_TOTAL);

    dim3 g1(G4 / 64, (S_LEN * BATCH) / 64);
    xproj_gemm<<<g1, 256>>>(x, eWih0, eBih0, eBhh0);
    lstm_persistent<<<NBLK, 256, SMEM_TOTAL>>>(eWhh0, eWih, eBih, eBhh,
                                               dWih, dBih, dBhh, linW, linB,
                                               out, out_size);
}

// round 13
// speedup vs baseline: 2.4269x; 1.7226x over previous
#include <cuda_runtime.h>
#include <cuda_bf16.h>
#include <cstdint>

typedef unsigned long long ull;

#define S_LEN 256
#define BATCH 64
#define FEAT  256
#define HID   768
#define G4    3072
#define TLEN  32
#define NBLK  128
#define TM    6
#define OUT_ENC_OFF (TLEN*BATCH*FEAT)
#define ENC_SZ (BATCH*HID)

// ---- dynamic smem layout for persistent kernel (bytes) ----
#define WSTRIDE  770                       // ulls per jj row (bank spread)
#define OFF_W    0
#define SZ_W     (24*WSTRIDE*8)            // 147840
#define OFF_RED  (OFF_W + SZ_W)
#define SZ_RED   (4*32*25*8)               // 25600
#define OFF_GT   (OFF_RED + SZ_RED)
#define SZ_GT    (24*64*4)                 // 6144
#define OFF_C    (OFF_GT + SZ_GT)
#define SZ_C     (384*4)
#define SMEM_TOTAL (OFF_C + SZ_C)          // 181120

// ---- static device scratch ----
// xproj permuted: [t][blk][b][jj], jj = gate*6+ml  (1536 floats per (t,blk))
__device__ __align__(16) float g_xproj[(size_t)S_LEN*NBLK*BATCH*24];
// h TRANSPOSED: [m(768)][b(64)]
__device__ __align__(16) float g_hT[2][HID*BATCH];
__device__ __align__(16) float g_dh[2][HID];
__device__ unsigned g_bar_count;
__device__ volatile unsigned g_bar_gen;

// ---- helpers ----
__device__ __forceinline__ float sigf(float x) { return 1.0f / (1.0f + __expf(-x)); }
__device__ __forceinline__ float tanhfast(float x) {
    float t = __expf(-2.0f * fabsf(x));
    float r = (1.0f - t) / (1.0f + t);
    return copysignf(r, x);
}
__device__ __forceinline__ float warp_sum(float v) {
#pragma unroll
    for (int o = 16; o; o >>= 1) v += __shfl_xor_sync(0xffffffffu, v, o);
    return v;
}
__device__ __forceinline__ void ffma2(ull &acc, ull a, ull b) {
    asm("fma.rn.f32x2 %0, %1, %2, %0;" : "+l"(acc) : "l"(a), "l"(b));
}
__device__ __forceinline__ void add2(ull &a, ull b) {
    asm("add.rn.f32x2 %0, %0, %1;" : "+l"(a) : "l"(b));
}
__device__ __forceinline__ ull dup2(float x) {
    ull r; asm("mov.b64 %0, {%1, %1};" : "=l"(r) : "f"(x)); return r;
}
__device__ __forceinline__ float2 unpack2(ull v) {
    float2 r; asm("mov.b64 {%0, %1}, %2;" : "=f"(r.x), "=f"(r.y) : "l"(v)); return r;
}
__device__ __forceinline__ ulonglong2 ldcg2(const float* p) {
    ulonglong2 r;
    asm volatile("ld.global.cg.v2.u64 {%0,%1},[%2];"
                 : "=l"(r.x), "=l"(r.y) : "l"(p));
    return r;
}

__device__ __forceinline__ void gsync(unsigned &my_gen) {
    __syncthreads();
    if (threadIdx.x == 0) {
        __threadfence();
        if (atomicAdd(&g_bar_count, 1u) == NBLK - 1u) {
            atomicExch(&g_bar_count, 0u);
            __threadfence();
            g_bar_gen = my_gen + 1u;
        } else {
            while (g_bar_gen == my_gen) { __nanosleep(64); }
            __threadfence();
        }
    }
    my_gen += 1u;
    __syncthreads();
}

// ---------------------------------------------------------------------------
// Kernel 1: xproj = x @ Wih0^T + (bih0+bhh0), permuted output.
// M=16384, N=3072, K=256. Tile 128x128, 256 threads, micro 8m x 8j (FFMA2).
// ---------------------------------------------------------------------------
__global__ void __launch_bounds__(256, 2) xproj_gemm(
    const float* __restrict__ X, const float* __restrict__ W,
    const float* __restrict__ bA, const float* __restrict__ bB)
{
    __shared__ __align__(16) float sX[16 * 132];   // [k][m]
    __shared__ __align__(16) float sWk[16 * 132];  // [k][j]
    const int tid = threadIdx.x;
    const int jBase = blockIdx.x * 128;
    const int mBase = blockIdx.y * 128;
    const int tx = tid & 15, ty = tid >> 4;
    const int lm = tid & 127;
    const int q2 = (tid >> 7) * 2;

    ull acc[8][4];
#pragma unroll
    for (int m = 0; m < 8; m++)
#pragma unroll
        for (int jp = 0; jp < 4; jp++) acc[m][jp] = 0ull;

    for (int k0 = 0; k0 < 256; k0 += 16) {
        const float* Xr = X + (size_t)(mBase + lm) * 256 + k0;
        const float* Wr = W + (size_t)(jBase + lm) * 256 + k0;
        float4 xv0 = *(const float4*)(Xr + q2 * 4);
        float4 xv1 = *(const float4*)(Xr + q2 * 4 + 4);
        float4 wv0 = *(const float4*)(Wr + q2 * 4);
        float4 wv1 = *(const float4*)(Wr + q2 * 4 + 4);
        __syncthreads();
        {
            int kb = q2 * 4;
            sX[(kb + 0) * 132 + lm] = xv0.x; sX[(kb + 1) * 132 + lm] = xv0.y;
            sX[(kb + 2) * 132 + lm] = xv0.z; sX[(kb + 3) * 132 + lm] = xv0.w;
            sX[(kb + 4) * 132 + lm] = xv1.x; sX[(kb + 5) * 132 + lm] = xv1.y;
            sX[(kb + 6) * 132 + lm] = xv1.z; sX[(kb + 7) * 132 + lm] = xv1.w;
            sWk[(kb + 0) * 132 + lm] = wv0.x; sWk[(kb + 1) * 132 + lm] = wv0.y;
            sWk[(kb + 2) * 132 + lm] = wv0.z; sWk[(kb + 3) * 132 + lm] = wv0.w;
            sWk[(kb + 4) * 132 + lm] = wv1.x; sWk[(kb + 5) * 132 + lm] = wv1.y;
            sWk[(kb + 6) * 132 + lm] = wv1.z; sWk[(kb + 7) * 132 + lm] = wv1.w;
        }
        __syncthreads();
#pragma unroll
        for (int k = 0; k < 16; k++) {
            float4 xa = *(const float4*)(sX + k * 132 + ty * 8);
            float4 xb = *(const float4*)(sX + k * 132 + ty * 8 + 4);
            ull d0 = dup2(xa.x), d1 = dup2(xa.y), d2 = dup2(xa.z), d3 = dup2(xa.w);
            ull d4 = dup2(xb.x), d5 = dup2(xb.y), d6 = dup2(xb.z), d7 = dup2(xb.w);
            // interleaved pair assignment: thread tx owns pairs {tx, tx+16, tx+32, tx+48}
#pragma unroll
            for (int jp = 0; jp < 4; jp++) {
                ull wv = *(const ull*)(sWk + k * 132 + (tx + jp * 16) * 2);
                ffma2(acc[0][jp], d0, wv); ffma2(acc[1][jp], d1, wv);
                ffma2(acc[2][jp], d2, wv); ffma2(acc[3][jp], d3, wv);
                ffma2(acc[4][jp], d4, wv); ffma2(acc[5][jp], d5, wv);
                ffma2(acc[6][jp], d6, wv); ffma2(acc[7][jp], d7, wv);
            }
        }
    }

    // epilogue: bias + scatter to permuted layout
#pragma unroll
    for (int jp = 0; jp < 4; jp++) {
        int j0 = jBase + (tx + jp * 16) * 2;
        float bb0 = bA[j0] + bB[j0];
        float bb1 = bA[j0 + 1] + bB[j0 + 1];
#pragma unroll
        for (int m = 0; m < 8; m++) {
            int mg = mBase + ty * 8 + m;
            int t = mg >> 6, b = mg & 63;
            float2 u = unpack2(acc[m][jp]);
            float v0 = u.x + bb0, v1 = u.y + bb1;
            int r0 = j0 % HID, gate0 = j0 / HID;
            // j0 even, pair within same 6-block only if r0%6<5 — do both separately
            g_xproj[(((size_t)t * NBLK + (r0 / 6)) * BATCH + b) * 24 + gate0 * 6 + (r0 % 6)] = v0;
            int j1 = j0 + 1;
            int r1 = j1 % HID, gate1 = j1 / HID;
            g_xproj[(((size_t)t * NBLK + (r1 / 6)) * BATCH + b) * 24 + gate1 * 6 + (r1 % 6)] = v1;
        }
    }
}

// ---------------------------------------------------------------------------
// load 24 gate-rows (dup'd f32x2) into smem: sW[jj*WSTRIDE + k]
// ---------------------------------------------------------------------------
__device__ __forceinline__ void load_weights_dup(
    const float* __restrict__ W, int m0, int tid, ull* sW)
{
    for (int i = tid; i < 24 * HID; i += 256) {
        int jj = i / HID;
        int k = i - jj * HID;
        int gate = jj / 6, ml = jj - gate * 6;
        float w = W[(size_t)(gate * HID + m0 + ml) * HID + k];
        sW[(size_t)jj * WSTRIDE + k] = dup2(w);
    }
}

// ---------------------------------------------------------------------------
// gates sweep: 8 warps x 96-k slices, full 64b x 24j tile each; tree-reduce
// into sGt[jj*64 + b].
// ---------------------------------------------------------------------------
__device__ __forceinline__ void loadgrp(ull* buf, const float* hp) {
#pragma unroll
    for (int q = 0; q < 4; q++) {
        ulonglong2 a = ldcg2(hp + q * 64);
        ulonglong2 b = ldcg2(hp + q * 64 + 4);
        buf[q * 4 + 0] = a.x; buf[q * 4 + 1] = a.y;
        buf[q * 4 + 2] = b.x; buf[q * 4 + 3] = b.y;
    }
}

__device__ __forceinline__ void gates_sweep(
    const float* __restrict__ hT, const ull* sW, ull* sRed, float* sGt, int tid)
{
    const int lane = tid & 31, w = tid >> 5;
    const int bg = lane & 7, jg = lane >> 3;
    const int b0 = bg * 8;
    const int kw = w * 96;

    const ull* wr0 = sW + (size_t)(jg * 6 + 0) * WSTRIDE + kw;
    const ull* wr1 = sW + (size_t)(jg * 6 + 1) * WSTRIDE + kw;
    const ull* wr2 = sW + (size_t)(jg * 6 + 2) * WSTRIDE + kw;
    const ull* wr3 = sW + (size_t)(jg * 6 + 3) * WSTRIDE + kw;
    const ull* wr4 = sW + (size_t)(jg * 6 + 4) * WSTRIDE + kw;
    const ull* wr5 = sW + (size_t)(jg * 6 + 5) * WSTRIDE + kw;

    ull acc[6][4];
#pragma unroll
    for (int jr = 0; jr < 6; jr++)
#pragma unroll
        for (int bp = 0; bp < 4; bp++) acc[jr][bp] = 0ull;

    const float* hp = hT + (size_t)kw * 64 + b0;
    ull bufA[16], bufB[16];
    loadgrp(bufA, hp);

#pragma unroll 1
    for (int g = 0; g < 24; g += 2) {
        if (g + 1 < 24) loadgrp(bufB, hp + (g + 1) * 4 * 64);
#pragma unroll
        for (int q = 0; q < 4; q++) {
            int kk = g * 4 + q;
            ull w0 = wr0[kk], w1 = wr1[kk], w2 = wr2[kk];
            ull w3 = wr3[kk], w4 = wr4[kk], w5 = wr5[kk];
            ull h0 = bufA[q * 4 + 0], h1 = bufA[q * 4 + 1];
            ull h2 = bufA[q * 4 + 2], h3 = bufA[q * 4 + 3];
            ffma2(acc[0][0], h0, w0); ffma2(acc[0][1], h1, w0); ffma2(acc[0][2], h2, w0); ffma2(acc[0][3], h3, w0);
            ffma2(acc[1][0], h0, w1); ffma2(acc[1][1], h1, w1); ffma2(acc[1][2], h2, w1); ffma2(acc[1][3], h3, w1);
            ffma2(acc[2][0], h0, w2); ffma2(acc[2][1], h1, w2); ffma2(acc[2][2], h2, w2); ffma2(acc[2][3], h3, w2);
            ffma2(acc[3][0], h0, w3); ffma2(acc[3][1], h1, w3); ffma2(acc[3][2], h2, w3); ffma2(acc[3][3], h3, w3);
            ffma2(acc[4][0], h0, w4); ffma2(acc[4][1], h1, w4); ffma2(acc[4][2], h2, w4); ffma2(acc[4][3], h3, w4);
            ffma2(acc[5][0], h0, w5); ffma2(acc[5][1], h1, w5); ffma2(acc[5][2], h2, w5); ffma2(acc[5][3], h3, w5);
        }
        if (g + 2 < 24) loadgrp(bufA, hp + (g + 2) * 4 * 64);
#pragma unroll
        for (int q = 0; q < 4; q++) {
            int kk = g * 4 + 4 + q;
            ull w0 = wr0[kk], w1 = wr1[kk], w2 = wr2[kk];
            ull w3 = wr3[kk], w4 = wr4[kk], w5 = wr5[kk];
            ull h0 = bufB[q * 4 + 0], h1 = bufB[q * 4 + 1];
            ull h2 = bufB[q * 4 + 2], h3 = bufB[q * 4 + 3];
            ffma2(acc[0][0], h0, w0); ffma2(acc[0][1], h1, w0); ffma2(acc[0][2], h2, w0); ffma2(acc[0][3], h3, w0);
            ffma2(acc[1][0], h0, w1); ffma2(acc[1][1], h1, w1); ffma2(acc[1][2], h2, w1); ffma2(acc[1][3], h3, w1);
            ffma2(acc[2][0], h0, w2); ffma2(acc[2][1], h1, w2); ffma2(acc[2][2], h2, w2); ffma2(acc[2][3], h3, w2);
            ffma2(acc[3][0], h0, w3); ffma2(acc[3][1], h1, w3); ffma2(acc[3][2], h2, w3); ffma2(acc[3][3], h3, w3);
            ffma2(acc[4][0], h0, w4); ffma2(acc[4][1], h1, w4); ffma2(acc[4][2], h2, w4); ffma2(acc[4][3], h3, w4);
            ffma2(acc[5][0], h0, w5); ffma2(acc[5][1], h1, w5); ffma2(acc[5][2], h2, w5); ffma2(acc[5][3], h3, w5);
        }
    }

    // tree reduction: 8 -> 4 -> 2 -> 1 warps
    ull* slot;
    slot = sRed + (size_t)(w & 3) * (32 * 25) + (size_t)lane * 25;
    if (w >= 4) {
#pragma unroll
        for (int jr = 0; jr < 6; jr++)
#pragma unroll
            for (int bp = 0; bp < 4; bp++) slot[jr * 4 + bp] = acc[jr][bp];
    }
    __syncthreads();
    if (w < 4) {
#pragma unroll
        for (int jr = 0; jr < 6; jr++)
#pragma unroll
            for (int bp = 0; bp < 4; bp++) add2(acc[jr][bp], slot[jr * 4 + bp]);
    }
    __syncthreads();
    slot = sRed + (size_t)(w & 1) * (32 * 25) + (size_t)lane * 25;
    if (w == 2 || w == 3) {
#pragma unroll
        for (int jr = 0; jr < 6; jr++)
#pragma unroll
            for (int bp = 0; bp < 4; bp++) slot[jr * 4 + bp] = acc[jr][bp];
    }
    __syncthreads();
    if (w < 2) {
#pragma unroll
        for (int jr = 0; jr < 6; jr++)
#pragma unroll
            for (int bp = 0; bp < 4; bp++) add2(acc[jr][bp], slot[jr * 4 + bp]);
    }
    __syncthreads();
    slot = sRed + (size_t)lane * 25;
    if (w == 1) {
#pragma unroll
        for (int jr = 0; jr < 6; jr++)
#pragma unroll
            for (int bp = 0; bp < 4; bp++) slot[jr * 4 + bp] = acc[jr][bp];
    }
    __syncthreads();
    if (w == 0) {
#pragma unroll
        for (int jr = 0; jr < 6; jr++)
#pragma unroll
            for (int bp = 0; bp < 4; bp++) {
                add2(acc[jr][bp], slot[jr * 4 + bp]);
                *(ull*)(sGt + (jg * 6 + jr) * 64 + b0 + bp * 2) = acc[jr][bp];
            }
    }
    __syncthreads();
}

// ---------------------------------------------------------------------------
// Kernel 2: persistent
// ---------------------------------------------------------------------------
__global__ void __launch_bounds__(256, 1) lstm_persistent(
    const float* __restrict__ Whh0,
    const float* __restrict__ eWih, const float* __restrict__ eBih,
    const float* __restrict__ eBhh,
    const float* __restrict__ dWih, const float* __restrict__ dBih,
    const float* __restrict__ dBhh,
    const float* __restrict__ linW, const float* __restrict__ linB,
    float* __restrict__ out, int out_size)
{
    extern __shared__ __align__(16) unsigned char smem[];
    ull*   sW   = (ull*)(smem + OFF_W);
    ull*   sRed = (ull*)(smem + OFF_RED);
    float* sGt  = (float*)(smem + OFF_GT);
    float* sC   = (float*)(smem + OFF_C);

    const int tid = threadIdx.x;
    const int blk = blockIdx.x;
    const int m0 = blk * TM;
    const int lane = tid & 31, warp = tid >> 5;
    unsigned my_gen = g_bar_gen;

    // init: zero h[0], smem c, decoder h
    for (int i = blk * 384 + tid; i < blk * 384 + 384; i += 256) g_hT[0][i] = 0.0f;
    if (tid < 128) sC[tid + 256] = 0.0f;
    sC[tid] = 0.0f;
    if (blk < 3) g_dh[0][blk * 256 + tid] = 0.0f;

    load_weights_dup(Whh0, m0, tid, sW);
    gsync(my_gen);

    const bool wrEnc = (out_size >= OUT_ENC_OFF + 3 * ENC_SZ);
    const int b_0 = tid / 6, ml_0 = tid - (tid / 6) * 6;
    const int idx1 = tid + 256;
    const int b_1 = idx1 / 6, ml_1 = idx1 - (idx1 / 6) * 6;
    int cur = 0;

    // ---- Phase A: encoder layer 0, 256 serial steps ----
#pragma unroll 1
    for (int t = 0; t < S_LEN; t++) {
        const float* aX = g_xproj + ((size_t)t * NBLK + blk) * 1536;
        float ax0[4], ax1[4];
#pragma unroll
        for (int g4 = 0; g4 < 4; g4++) ax0[g4] = aX[b_0 * 24 + g4 * 6 + ml_0];
        if (tid < 128) {
#pragma unroll
            for (int g4 = 0; g4 < 4; g4++) ax1[g4] = aX[b_1 * 24 + g4 * 6 + ml_1];
        }

        gates_sweep(g_hT[cur], sW, sRed, sGt, tid);

        {
            float iv = sGt[(0 + ml_0) * 64 + b_0] + ax0[0];
            float fv = sGt[(6 + ml_0) * 64 + b_0] + ax0[1];
            float gv = sGt[(12 + ml_0) * 64 + b_0] + ax0[2];
            float ov = sGt[(18 + ml_0) * 64 + b_0] + ax0[3];
            float c = sigf(fv) * sC[tid] + sigf(iv) * tanhfast(gv);
            sC[tid] = c;
            g_hT[cur ^ 1][(m0 + ml_0) * 64 + b_0] = sigf(ov) * tanhfast(c);
        }
        if (tid < 128) {
            float iv = sGt[(0 + ml_1) * 64 + b_1] + ax1[0];
            float fv = sGt[(6 + ml_1) * 64 + b_1] + ax1[1];
            float gv = sGt[(12 + ml_1) * 64 + b_1] + ax1[2];
            float ov = sGt[(18 + ml_1) * 64 + b_1] + ax1[3];
            float c = sigf(fv) * sC[idx1] + sigf(iv) * tanhfast(gv);
            sC[idx1] = c;
            g_hT[cur ^ 1][(m0 + ml_1) * 64 + b_1] = sigf(ov) * tanhfast(c);
        }
        gsync(my_gen);
        cur ^= 1;
    }

    if (wrEnc) {
        out[OUT_ENC_OFF + b_0 * HID + m0 + ml_0] = g_hT[cur][(m0 + ml_0) * 64 + b_0];
        if (tid < 128)
            out[OUT_ENC_OFF + b_1 * HID + m0 + ml_1] = g_hT[cur][(m0 + ml_1) * 64 + b_1];
    }

    // ---- Phase C: encoder layers 1..2 (zero state -> f-gate dead) ----
    for (int l = 0; l < 2; l++) {
        load_weights_dup(eWih + (size_t)l * G4 * HID, m0, tid, sW);
        __syncthreads();
        gates_sweep(g_hT[cur], sW, sRed, sGt, tid);
        {
            float iv = sGt[(0 + ml_0) * 64 + b_0] + eBih[l * G4 + 0 * HID + m0 + ml_0] + eBhh[l * G4 + 0 * HID + m0 + ml_0];
            float gv = sGt[(12 + ml_0) * 64 + b_0] + eBih[l * G4 + 2 * HID + m0 + ml_0] + eBhh[l * G4 + 2 * HID + m0 + ml_0];
            float ov = sGt[(18 + ml_0) * 64 + b_0] + eBih[l * G4 + 3 * HID + m0 + ml_0] + eBhh[l * G4 + 3 * HID + m0 + ml_0];
            float c = sigf(iv) * tanhfast(gv);
            float h = sigf(ov) * tanhfast(c);
            g_hT[cur ^ 1][(m0 + ml_0) * 64 + b_0] = h;
            if (wrEnc) out[OUT_ENC_OFF + (l + 1) * ENC_SZ + b_0 * HID + m0 + ml_0] = h;
        }
        if (tid < 128) {
            float iv = sGt[(0 + ml_1) * 64 + b_1] + eBih[l * G4 + 0 * HID + m0 + ml_1] + eBhh[l * G4 + 0 * HID + m0 + ml_1];
            float gv = sGt[(12 + ml_1) * 64 + b_1] + eBih[l * G4 + 2 * HID + m0 + ml_1] + eBhh[l * G4 + 2 * HID + m0 + ml_1];
            float ov = sGt[(18 + ml_1) * 64 + b_1] + eBih[l * G4 + 3 * HID + m0 + ml_1] + eBhh[l * G4 + 3 * HID + m0 + ml_1];
            float c = sigf(iv) * tanhfast(gv);
            float h = sigf(ov) * tanhfast(c);
            g_hT[cur ^ 1][(m0 + ml_1) * 64 + b_1] = h;
            if (wrEnc) out[OUT_ENC_OFF + (l + 1) * ENC_SZ + b_1 * HID + m0 + ml_1] = h;
        }
        gsync(my_gen);
        cur ^= 1;
    }

    // ---- Phase D: decoder — batch-independent; only layer-2 chain feeds the
    // head; f-gate dead (c_prev == 0). B=1 matvec chain + broadcast head. ----
    const int gw = blk * 8 + warp;  // 0..1023
    int dc = 0;
    for (int t = 0; t < TLEN; t++) {
        const float* hsrc = g_dh[dc];
        for (int m = gw; m < HID; m += NBLK * 8) {
            const float* wi = dWih + ((size_t)2 * G4 + 0 * HID + m) * HID;
            const float* wg = dWih + ((size_t)2 * G4 + 2 * HID + m) * HID;
            const float* wo = dWih + ((size_t)2 * G4 + 3 * HID + m) * HID;
            float ai = 0.0f, ag = 0.0f, ao = 0.0f;
            for (int k = lane; k < HID; k += 32) {
                float hv = __ldcg(hsrc + k);
                ai += wi[k] * hv; ag += wg[k] * hv; ao += wo[k] * hv;
            }
            ai = warp_sum(ai); ag = warp_sum(ag); ao = warp_sum(ao);
            if (lane == 0) {
                int bi = 2 * G4 + m;
                float iv = ai + dBih[bi] + dBhh[bi];
                float gv = ag + dBih[bi + 2 * HID] + dBhh[bi + 2 * HID];
                float ov = ao + dBih[bi + 3 * HID] + dBhh[bi + 3 * HID];
                float c = sigf(iv) * tanhfast(gv);
                g_dh[dc ^ 1][m] = sigf(ov) * tanhfast(c);
            }
        }
        gsync(my_gen);
        if (gw < FEAT) {
            const float* wr = linW + (size_t)gw * HID;
            float a = 0.0f;
            for (int k = lane; k < HID; k += 32) a += wr[k] * __ldcg(g_dh[dc ^ 1] + k);
            a = warp_sum(a) + linB[gw];
            float* op = out + (size_t)t * BATCH * FEAT + gw;
            op[(size_t)lane * FEAT] = a;
            op[(size_t)(lane + 32) * FEAT] = a;
        }
        dc ^= 1;
    }
}

extern "C" void kernel_launch(void* const* d_in, const int* in_sizes, int n_in,
                              void* d_out, int out_size) {
    const float* x      = (const float*)d_in[0];
    const float* eWih0  = (const float*)d_in[1];
    const float* eWhh0  = (const float*)d_in[2];
    const float* eBih0  = (const float*)d_in[3];
    const float* eBhh0  = (const float*)d_in[4];
    const float* eWih   = (const float*)d_in[5];
    // d_in[6] = e_Whh : unused (zero-state layers)
    const float* eBih   = (const float*)d_in[7];
    const float* eBhh   = (const float*)d_in[8];
    const float* dWih   = (const float*)d_in[9];
    // d_in[10] = d_Whh : unused
    const float* dBih   = (const float*)d_in[11];
    const float* dBhh   = (const float*)d_in[12];
    const float* linW   = (const float*)d_in[13];
    const float* linB   = (const float*)d_in[14];
    float* out = (float*)d_out;

    cudaFuncSetAttribute(lstm_persistent,
                         cudaFuncAttributeMaxDynamicSharedMemorySize, SMEM_TOTAL);

    dim3 g1(G4 / 128, (S_LEN * BATCH) / 128);
    xproj_gemm<<<g1, 256>>>(x, eWih0, eBih0, eBhh0);
    lstm_persistent<<<NBLK, 256, SMEM_TOTAL>>>(eWhh0, eWih, eBih, eBhh,
                                               dWih, dBih, dBhh, linW, linB,
                                               out, out_size);
}

// round 14
// speedup vs baseline: 2.4590x; 1.0132x over previous
#include <cuda_runtime.h>
#include <cuda_bf16.h>
#include <cstdint>

typedef unsigned long long ull;

#define S_LEN 256
#define BATCH 64
#define FEAT  256
#define HID   768
#define G4    3072
#define TLEN  32
#define NBLK  128
#define TM    6
#define PTHR  512
#define OUT_ENC_OFF (TLEN*BATCH*FEAT)
#define ENC_SZ (BATCH*HID)

// ---- dynamic smem layout for persistent kernel (bytes) ----
#define WSTRIDE  770                       // ulls per jj row (bank spread, even)
#define OFF_W    0
#define SZ_W     (24*WSTRIDE*8)            // 147840
#define OFF_RED  (OFF_W + SZ_W)
#define SZ_RED   (8*32*25*8)               // 51200
#define OFF_GT   (OFF_RED + SZ_RED)
#define SZ_GT    (24*64*4)                 // 6144
#define OFF_C    (OFF_GT + SZ_GT)
#define SZ_C     (384*4)
#define SMEM_TOTAL (OFF_C + SZ_C)          // 206720

// ---- static device scratch ----
// xproj permuted: [t][blk][b][jj], jj = gate*6+ml  (1536 floats per (t,blk))
__device__ __align__(16) float g_xproj[(size_t)S_LEN*NBLK*BATCH*24];
// h TRANSPOSED: [m(768)][b(64)]
__device__ __align__(16) float g_hT[2][HID*BATCH];
__device__ __align__(16) float g_dh[2][HID];
__device__ unsigned g_bar_count;
__device__ volatile unsigned g_bar_gen;

// ---- helpers ----
__device__ __forceinline__ float sigf(float x) { return 1.0f / (1.0f + __expf(-x)); }
__device__ __forceinline__ float tanhfast(float x) {
    float t = __expf(-2.0f * fabsf(x));
    float r = (1.0f - t) / (1.0f + t);
    return copysignf(r, x);
}
__device__ __forceinline__ float warp_sum(float v) {
#pragma unroll
    for (int o = 16; o; o >>= 1) v += __shfl_xor_sync(0xffffffffu, v, o);
    return v;
}
__device__ __forceinline__ void ffma2(ull &acc, ull a, ull b) {
    asm("fma.rn.f32x2 %0, %1, %2, %0;" : "+l"(acc) : "l"(a), "l"(b));
}
__device__ __forceinline__ void add2(ull &a, ull b) {
    asm("add.rn.f32x2 %0, %0, %1;" : "+l"(a) : "l"(b));
}
__device__ __forceinline__ ull dup2(float x) {
    ull r; asm("mov.b64 %0, {%1, %1};" : "=l"(r) : "f"(x)); return r;
}
__device__ __forceinline__ float2 unpack2(ull v) {
    float2 r; asm("mov.b64 {%0, %1}, %2;" : "=f"(r.x), "=f"(r.y) : "l"(v)); return r;
}
__device__ __forceinline__ ulonglong2 ldcg2(const float* p) {
    ulonglong2 r;
    asm volatile("ld.global.cg.v2.u64 {%0,%1},[%2];"
                 : "=l"(r.x), "=l"(r.y) : "l"(p));
    return r;
}

__device__ __forceinline__ void gsync(unsigned &my_gen) {
    __syncthreads();
    if (threadIdx.x == 0) {
        __threadfence();
        if (atomicAdd(&g_bar_count, 1u) == NBLK - 1u) {
            atomicExch(&g_bar_count, 0u);
            __threadfence();
            g_bar_gen = my_gen + 1u;
        } else {
            while (g_bar_gen == my_gen) { __nanosleep(32); }
            __threadfence();
        }
    }
    my_gen += 1u;
    __syncthreads();
}

// ---------------------------------------------------------------------------
// Kernel 1: xproj = x @ Wih0^T + (bih0+bhh0), permuted output.
// M=16384, N=3072, K=256. Tile 128x128, 256 threads, micro 8m x 8j (FFMA2).
// ---------------------------------------------------------------------------
__global__ void __launch_bounds__(256, 2) xproj_gemm(
    const float* __restrict__ X, const float* __restrict__ W,
    const float* __restrict__ bA, const float* __restrict__ bB)
{
    __shared__ __align__(16) float sX[16 * 132];   // [k][m]
    __shared__ __align__(16) float sWk[16 * 132];  // [k][j]
    const int tid = threadIdx.x;
    const int jBase = blockIdx.x * 128;
    const int mBase = blockIdx.y * 128;
    const int tx = tid & 15, ty = tid >> 4;
    const int lm = tid & 127;
    const int q2 = (tid >> 7) * 2;

    ull acc[8][4];
#pragma unroll
    for (int m = 0; m < 8; m++)
#pragma unroll
        for (int jp = 0; jp < 4; jp++) acc[m][jp] = 0ull;

    for (int k0 = 0; k0 < 256; k0 += 16) {
        const float* Xr = X + (size_t)(mBase + lm) * 256 + k0;
        const float* Wr = W + (size_t)(jBase + lm) * 256 + k0;
        float4 xv0 = *(const float4*)(Xr + q2 * 4);
        float4 xv1 = *(const float4*)(Xr + q2 * 4 + 4);
        float4 wv0 = *(const float4*)(Wr + q2 * 4);
        float4 wv1 = *(const float4*)(Wr + q2 * 4 + 4);
        __syncthreads();
        {
            int kb = q2 * 4;
            sX[(kb + 0) * 132 + lm] = xv0.x; sX[(kb + 1) * 132 + lm] = xv0.y;
            sX[(kb + 2) * 132 + lm] = xv0.z; sX[(kb + 3) * 132 + lm] = xv0.w;
            sX[(kb + 4) * 132 + lm] = xv1.x; sX[(kb + 5) * 132 + lm] = xv1.y;
            sX[(kb + 6) * 132 + lm] = xv1.z; sX[(kb + 7) * 132 + lm] = xv1.w;
            sWk[(kb + 0) * 132 + lm] = wv0.x; sWk[(kb + 1) * 132 + lm] = wv0.y;
            sWk[(kb + 2) * 132 + lm] = wv0.z; sWk[(kb + 3) * 132 + lm] = wv0.w;
            sWk[(kb + 4) * 132 + lm] = wv1.x; sWk[(kb + 5) * 132 + lm] = wv1.y;
            sWk[(kb + 6) * 132 + lm] = wv1.z; sWk[(kb + 7) * 132 + lm] = wv1.w;
        }
        __syncthreads();
#pragma unroll
        for (int k = 0; k < 16; k++) {
            float4 xa = *(const float4*)(sX + k * 132 + ty * 8);
            float4 xb = *(const float4*)(sX + k * 132 + ty * 8 + 4);
            ull d0 = dup2(xa.x), d1 = dup2(xa.y), d2 = dup2(xa.z), d3 = dup2(xa.w);
            ull d4 = dup2(xb.x), d5 = dup2(xb.y), d6 = dup2(xb.z), d7 = dup2(xb.w);
#pragma unroll
            for (int jp = 0; jp < 4; jp++) {
                ull wv = *(const ull*)(sWk + k * 132 + (tx + jp * 16) * 2);
                ffma2(acc[0][jp], d0, wv); ffma2(acc[1][jp], d1, wv);
                ffma2(acc[2][jp], d2, wv); ffma2(acc[3][jp], d3, wv);
                ffma2(acc[4][jp], d4, wv); ffma2(acc[5][jp], d5, wv);
                ffma2(acc[6][jp], d6, wv); ffma2(acc[7][jp], d7, wv);
            }
        }
    }

#pragma unroll
    for (int jp = 0; jp < 4; jp++) {
        int j0 = jBase + (tx + jp * 16) * 2;
        float bb0 = bA[j0] + bB[j0];
        float bb1 = bA[j0 + 1] + bB[j0 + 1];
#pragma unroll
        for (int m = 0; m < 8; m++) {
            int mg = mBase + ty * 8 + m;
            int t = mg >> 6, b = mg & 63;
            float2 u = unpack2(acc[m][jp]);
            int r0 = j0 % HID, gate0 = j0 / HID;
            g_xproj[(((size_t)t * NBLK + (r0 / 6)) * BATCH + b) * 24 + gate0 * 6 + (r0 % 6)] = u.x + bb0;
            int j1 = j0 + 1;
            int r1 = j1 % HID, gate1 = j1 / HID;
            g_xproj[(((size_t)t * NBLK + (r1 / 6)) * BATCH + b) * 24 + gate1 * 6 + (r1 % 6)] = u.y + bb1;
        }
    }
}

// ---------------------------------------------------------------------------
// load 24 gate-rows (dup'd f32x2) into smem: sW[jj*WSTRIDE + k]
// ---------------------------------------------------------------------------
__device__ __forceinline__ void load_weights_dup(
    const float* __restrict__ W, int m0, int tid, ull* sW)
{
    for (int i = tid; i < 24 * HID; i += PTHR) {
        int jj = i / HID;
        int k = i - jj * HID;
        int gate = jj / 6, ml = jj - gate * 6;
        float w = W[(size_t)(gate * HID + m0 + ml) * HID + k];
        sW[(size_t)jj * WSTRIDE + k] = dup2(w);
    }
}

// ---------------------------------------------------------------------------
// gates sweep: 16 warps x 48-k slices, full 64b x 24j tile; tree-reduce
// into sGt[jj*64 + b].
// ---------------------------------------------------------------------------
__device__ __forceinline__ void loadgrp2(ull* buf, const float* hp) {
    ulonglong2 a0 = ldcg2(hp);        // k  : b0..b3
    ulonglong2 a1 = ldcg2(hp + 4);    // k  : b4..b7
    ulonglong2 a2 = ldcg2(hp + 64);   // k+1: b0..b3
    ulonglong2 a3 = ldcg2(hp + 68);   // k+1: b4..b7
    buf[0] = a0.x; buf[1] = a0.y; buf[2] = a1.x; buf[3] = a1.y;
    buf[4] = a2.x; buf[5] = a2.y; buf[6] = a3.x; buf[7] = a3.y;
}

__device__ __forceinline__ void compute2k(
    ull acc[6][4], const ull* buf,
    const ull* wr0, const ull* wr1, const ull* wr2,
    const ull* wr3, const ull* wr4, const ull* wr5, int kk)
{
    {
        ulonglong2 w0 = *(const ulonglong2*)(wr0 + kk);
        ulonglong2 w1 = *(const ulonglong2*)(wr1 + kk);
        ulonglong2 w2 = *(const ulonglong2*)(wr2 + kk);
        ffma2(acc[0][0], buf[0], w0.x); ffma2(acc[0][1], buf[1], w0.x);
        ffma2(acc[0][2], buf[2], w0.x); ffma2(acc[0][3], buf[3], w0.x);
        ffma2(acc[1][0], buf[0], w1.x); ffma2(acc[1][1], buf[1], w1.x);
        ffma2(acc[1][2], buf[2], w1.x); ffma2(acc[1][3], buf[3], w1.x);
        ffma2(acc[2][0], buf[0], w2.x); ffma2(acc[2][1], buf[1], w2.x);
        ffma2(acc[2][2], buf[2], w2.x); ffma2(acc[2][3], buf[3], w2.x);
        ffma2(acc[0][0], buf[4], w0.y); ffma2(acc[0][1], buf[5], w0.y);
        ffma2(acc[0][2], buf[6], w0.y); ffma2(acc[0][3], buf[7], w0.y);
        ffma2(acc[1][0], buf[4], w1.y); ffma2(acc[1][1], buf[5], w1.y);
        ffma2(acc[1][2], buf[6], w1.y); ffma2(acc[1][3], buf[7], w1.y);
        ffma2(acc[2][0], buf[4], w2.y); ffma2(acc[2][1], buf[5], w2.y);
        ffma2(acc[2][2], buf[6], w2.y); ffma2(acc[2][3], buf[7], w2.y);
    }
    {
        ulonglong2 w3 = *(const ulonglong2*)(wr3 + kk);
        ulonglong2 w4 = *(const ulonglong2*)(wr4 + kk);
        ulonglong2 w5 = *(const ulonglong2*)(wr5 + kk);
        ffma2(acc[3][0], buf[0], w3.x); ffma2(acc[3][1], buf[1], w3.x);
        ffma2(acc[3][2], buf[2], w3.x); ffma2(acc[3][3], buf[3], w3.x);
        ffma2(acc[4][0], buf[0], w4.x); ffma2(acc[4][1], buf[1], w4.x);
        ffma2(acc[4][2], buf[2], w4.x); ffma2(acc[4][3], buf[3], w4.x);
        ffma2(acc[5][0], buf[0], w5.x); ffma2(acc[5][1], buf[1], w5.x);
        ffma2(acc[5][2], buf[2], w5.x); ffma2(acc[5][3], buf[3], w5.x);
        ffma2(acc[3][0], buf[4], w3.y); ffma2(acc[3][1], buf[5], w3.y);
        ffma2(acc[3][2], buf[6], w3.y); ffma2(acc[3][3], buf[7], w3.y);
        ffma2(acc[4][0], buf[4], w4.y); ffma2(acc[4][1], buf[5], w4.y);
        ffma2(acc[4][2], buf[6], w4.y); ffma2(acc[4][3], buf[7], w4.y);
        ffma2(acc[5][0], buf[4], w5.y); ffma2(acc[5][1], buf[5], w5.y);
        ffma2(acc[5][2], buf[6], w5.y); ffma2(acc[5][3], buf[7], w5.y);
    }
}

__device__ __forceinline__ void red_store(ull* slot, ull acc[6][4]) {
#pragma unroll
    for (int jr = 0; jr < 6; jr++)
#pragma unroll
        for (int bp = 0; bp < 4; bp++) slot[jr * 4 + bp] = acc[jr][bp];
}
__device__ __forceinline__ void red_add(ull acc[6][4], const ull* slot) {
#pragma unroll
    for (int jr = 0; jr < 6; jr++)
#pragma unroll
        for (int bp = 0; bp < 4; bp++) add2(acc[jr][bp], slot[jr * 4 + bp]);
}

__device__ __forceinline__ void gates_sweep(
    const float* __restrict__ hT, const ull* sW, ull* sRed, float* sGt, int tid)
{
    const int lane = tid & 31, w = tid >> 5;     // 16 warps
    const int bg = lane & 7, jg = lane >> 3;
    const int b0 = bg * 8;
    const int kw = w * 48;

    const ull* wr0 = sW + (size_t)(jg * 6 + 0) * WSTRIDE + kw;
    const ull* wr1 = sW + (size_t)(jg * 6 + 1) * WSTRIDE + kw;
    const ull* wr2 = sW + (size_t)(jg * 6 + 2) * WSTRIDE + kw;
    const ull* wr3 = sW + (size_t)(jg * 6 + 3) * WSTRIDE + kw;
    const ull* wr4 = sW + (size_t)(jg * 6 + 4) * WSTRIDE + kw;
    const ull* wr5 = sW + (size_t)(jg * 6 + 5) * WSTRIDE + kw;

    ull acc[6][4];
#pragma unroll
    for (int jr = 0; jr < 6; jr++)
#pragma unroll
        for (int bp = 0; bp < 4; bp++) acc[jr][bp] = 0ull;

    const float* hp = hT + (size_t)kw * 64 + b0;
    ull bufA[8], bufB[8];
    loadgrp2(bufA, hp);

#pragma unroll 1
    for (int g = 0; g < 24; g += 2) {
        if (g + 1 < 24) loadgrp2(bufB, hp + (size_t)(g + 1) * 128);
        compute2k(acc, bufA, wr0, wr1, wr2, wr3, wr4, wr5, g * 2);
        if (g + 2 < 24) loadgrp2(bufA, hp + (size_t)(g + 2) * 128);
        compute2k(acc, bufB, wr0, wr1, wr2, wr3, wr4, wr5, g * 2 + 2);
    }

    // tree reduction: 16 -> 8 -> 4 -> 2 -> 1 warps
    ull* slot;
    if (w >= 8) {
        slot = sRed + (size_t)(w - 8) * (32 * 25) + (size_t)lane * 25;
        red_store(slot, acc);
    }
    __syncthreads();
    if (w < 8) {
        slot = sRed + (size_t)w * (32 * 25) + (size_t)lane * 25;
        red_add(acc, slot);
    }
    __syncthreads();
    if (w >= 4 && w < 8) {
        slot = sRed + (size_t)(w - 4) * (32 * 25) + (size_t)lane * 25;
        red_store(slot, acc);
    }
    __syncthreads();
    if (w < 4) {
        slot = sRed + (size_t)w * (32 * 25) + (size_t)lane * 25;
        red_add(acc, slot);
    }
    __syncthreads();
    if (w == 2 || w == 3) {
        slot = sRed + (size_t)(w - 2) * (32 * 25) + (size_t)lane * 25;
        red_store(slot, acc);
    }
    __syncthreads();
    if (w < 2) {
        slot = sRed + (size_t)w * (32 * 25) + (size_t)lane * 25;
        red_add(acc, slot);
    }
    __syncthreads();
    if (w == 1) {
        slot = sRed + (size_t)lane * 25;
        red_store(slot, acc);
    }
    __syncthreads();
    if (w == 0) {
        slot = sRed + (size_t)lane * 25;
        red_add(acc, slot);
#pragma unroll
        for (int jr = 0; jr < 6; jr++)
#pragma unroll
            for (int bp = 0; bp < 4; bp++)
                *(ull*)(sGt + (jg * 6 + jr) * 64 + b0 + bp * 2) = acc[jr][bp];
    }
    __syncthreads();
}

// ---------------------------------------------------------------------------
// Kernel 2: persistent
// ---------------------------------------------------------------------------
__global__ void __launch_bounds__(PTHR, 1) lstm_persistent(
    const float* __restrict__ Whh0,
    const float* __restrict__ eWih, const float* __restrict__ eBih,
    const float* __restrict__ eBhh,
    const float* __restrict__ dWih, const float* __restrict__ dBih,
    const float* __restrict__ dBhh,
    const float* __restrict__ linW, const float* __restrict__ linB,
    float* __restrict__ out, int out_size)
{
    extern __shared__ __align__(16) unsigned char smem[];
    ull*   sW   = (ull*)(smem + OFF_W);
    ull*   sRed = (ull*)(smem + OFF_RED);
    float* sGt  = (float*)(smem + OFF_GT);
    float* sC   = (float*)(smem + OFF_C);

    const int tid = threadIdx.x;
    const int blk = blockIdx.x;
    const int m0 = blk * TM;
    const int lane = tid & 31, warp = tid >> 5;
    unsigned my_gen = g_bar_gen;

    // init: zero h[0] slice, smem c, decoder h
    if (tid < 384) {
        g_hT[0][blk * 384 + tid] = 0.0f;
        sC[tid] = 0.0f;
    }
    if (blk == 0) {
        g_dh[0][tid] = 0.0f;
        if (tid < 256) g_dh[0][PTHR + tid] = 0.0f;
    }

    load_weights_dup(Whh0, m0, tid, sW);
    gsync(my_gen);

    const bool wrEnc = (out_size >= OUT_ENC_OFF + 3 * ENC_SZ);
    const int b_0 = tid / 6, ml_0 = tid - (tid / 6) * 6;  // valid for tid<384
    int cur = 0;

    // ---- Phase A: encoder layer 0, 256 serial steps ----
#pragma unroll 1
    for (int t = 0; t < S_LEN; t++) {
        const float* aX = g_xproj + ((size_t)t * NBLK + blk) * 1536;
        float ax0[4];
        if (tid < 384) {
#pragma unroll
            for (int g4 = 0; g4 < 4; g4++) ax0[g4] = aX[b_0 * 24 + g4 * 6 + ml_0];
        }

        gates_sweep(g_hT[cur], sW, sRed, sGt, tid);

        if (tid < 384) {
            float iv = sGt[(0 + ml_0) * 64 + b_0] + ax0[0];
            float fv = sGt[(6 + ml_0) * 64 + b_0] + ax0[1];
            float gv = sGt[(12 + ml_0) * 64 + b_0] + ax0[2];
            float ov = sGt[(18 + ml_0) * 64 + b_0] + ax0[3];
            float c = sigf(fv) * sC[tid] + sigf(iv) * tanhfast(gv);
            sC[tid] = c;
            g_hT[cur ^ 1][(m0 + ml_0) * 64 + b_0] = sigf(ov) * tanhfast(c);
        }
        gsync(my_gen);
        cur ^= 1;
    }

    if (wrEnc && tid < 384)
        out[OUT_ENC_OFF + b_0 * HID + m0 + ml_0] = g_hT[cur][(m0 + ml_0) * 64 + b_0];

    // ---- Phase C: encoder layers 1..2 (zero state -> f-gate dead) ----
    for (int l = 0; l < 2; l++) {
        load_weights_dup(eWih + (size_t)l * G4 * HID, m0, tid, sW);
        __syncthreads();
        gates_sweep(g_hT[cur], sW, sRed, sGt, tid);
        if (tid < 384) {
            float iv = sGt[(0 + ml_0) * 64 + b_0] + eBih[l * G4 + 0 * HID + m0 + ml_0] + eBhh[l * G4 + 0 * HID + m0 + ml_0];
            float gv = sGt[(12 + ml_0) * 64 + b_0] + eBih[l * G4 + 2 * HID + m0 + ml_0] + eBhh[l * G4 + 2 * HID + m0 + ml_0];
            float ov = sGt[(18 + ml_0) * 64 + b_0] + eBih[l * G4 + 3 * HID + m0 + ml_0] + eBhh[l * G4 + 3 * HID + m0 + ml_0];
            float c = sigf(iv) * tanhfast(gv);
            float h = sigf(ov) * tanhfast(c);
            g_hT[cur ^ 1][(m0 + ml_0) * 64 + b_0] = h;
            if (wrEnc) out[OUT_ENC_OFF + (l + 1) * ENC_SZ + b_0 * HID + m0 + ml_0] = h;
        }
        gsync(my_gen);
        cur ^= 1;
    }

    // ---- Phase D: decoder — batch-independent; only layer-2 chain feeds the
    // head; f-gate dead (c_prev == 0). B=1 matvec chain + broadcast head. ----
    const int gw = blk * 16 + warp;  // 0..2047 global warps
    int dc = 0;
    for (int t = 0; t < TLEN; t++) {
        const float* hsrc = g_dh[dc];
        if (gw < HID) {
            int m = gw;
            const float* wi = dWih + ((size_t)2 * G4 + 0 * HID + m) * HID;
            const float* wg = dWih + ((size_t)2 * G4 + 2 * HID + m) * HID;
            const float* wo = dWih + ((size_t)2 * G4 + 3 * HID + m) * HID;
            float ai = 0.0f, ag = 0.0f, ao = 0.0f;
            for (int k = lane; k < HID; k += 32) {
                float hv = __ldcg(hsrc + k);
                ai += wi[k] * hv; ag += wg[k] * hv; ao += wo[k] * hv;
            }
            ai = warp_sum(ai); ag = warp_sum(ag); ao = warp_sum(ao);
            if (lane == 0) {
                int bi = 2 * G4 + m;
                float iv = ai + dBih[bi] + dBhh[bi];
                float gv = ag + dBih[bi + 2 * HID] + dBhh[bi + 2 * HID];
                float ov = ao + dBih[bi + 3 * HID] + dBhh[bi + 3 * HID];
                float c = sigf(iv) * tanhfast(gv);
                g_dh[dc ^ 1][m] = sigf(ov) * tanhfast(c);
            }
        }
        gsync(my_gen);
        if (gw < FEAT) {
            const float* wr = linW + (size_t)gw * HID;
            float a = 0.0f;
            for (int k = lane; k < HID; k += 32) a += wr[k] * __ldcg(g_dh[dc ^ 1] + k);
            a = warp_sum(a) + linB[gw];
            float* op = out + (size_t)t * BATCH * FEAT + gw;
            op[(size_t)lane * FEAT] = a;
            op[(size_t)(lane + 32) * FEAT] = a;
        }
        dc ^= 1;
    }
}

extern "C" void kernel_launch(void* const* d_in, const int* in_sizes, int n_in,
                              void* d_out, int out_size) {
    const float* x      = (const float*)d_in[0];
    const float* eWih0  = (const float*)d_in[1];
    const float* eWhh0  = (const float*)d_in[2];
    const float* eBih0  = (const float*)d_in[3];
    const float* eBhh0  = (const float*)d_in[4];
    const float* eWih   = (const float*)d_in[5];
    // d_in[6] = e_Whh : unused (zero-state layers)
    const float* eBih   = (const float*)d_in[7];
    const float* eBhh   = (const float*)d_in[8];
    const float* dWih   = (const float*)d_in[9];
    // d_in[10] = d_Whh : unused
    const float* dBih   = (const float*)d_in[11];
    const float* dBhh   = (const float*)d_in[12];
    const float* linW   = (const float*)d_in[13];
    const float* linB   = (const float*)d_in[14];
    float* out = (float*)d_out;

    cudaFuncSetAttribute(lstm_persistent,
                         cudaFuncAttributeMaxDynamicSharedMemorySize, SMEM_TOTAL);

    dim3 g1(G4 / 128, (S_LEN * BATCH) / 128);
    xproj_gemm<<<g1, 256>>>(x, eWih0, eBih0, eBhh0);
    lstm_persistent<<<NBLK, PTHR, SMEM_TOTAL>>>(eWhh0, eWih, eBih, eBhh,
                                                dWih, dBih, dBhh, linW, linB,
                                                out, out_size);
}